// round 4
// baseline (speedup 1.0000x reference)
#include <cuda_runtime.h>

// Fixed shapes from reference setup_inputs
#define BATCH   2
#define H_IN    64
#define W_IN    64
#define C_IN    128
#define N_IN    (H_IN * W_IN * C_IN)          // 524288
#define N_POOL  131072                        // 32*32*128
#define N_OUT   32

// Output layout: [w_zero (B*N_IN*N_OUT)] [b_u_ (B*N_OUT)] [w_zero] [b_l_ (B*N_OUT)]
#define WZ_ELEMS  ((long long)BATCH * N_IN * N_OUT)     // 33554432
#define OFF_BU    (WZ_ELEMS)                            // 33554432
#define OFF_WZ2   (OFF_BU + (long long)BATCH * N_OUT)   // 33554496
#define OFF_BL    (OFF_WZ2 + WZ_ELEMS)                  // 67108928

// float4-granular zero regions (both 16B aligned):
//   region0: float4 [0, 8388608)          -> floats [0, OFF_BU)
//   region1: float4 [8388624, 16777232)   -> floats [OFF_WZ2, OFF_BL)
#define REGION4      8388608LL
#define REGION1_OFF  8388624LL
#define TOTAL4       (2LL * REGION4)       // 16777216

// Role split: first NR blocks reduce, remaining NZ blocks zero.
// 1184 total = 8 CTAs/SM on 148 SMs = one full wave at 100% occupancy.
#define NR         296                      // 2 batches x 148 chunks
#define NZ         888
#define NBLK       (NR + NZ)                // 1184
#define R_THREADS  256
#define P_PER_BLK  886                      // ceil(131072/148)
#define Z_CHUNK    18894LL                  // ceil(TOTAL4 / NZ)

// ---------------------------------------------------------------------------
// Prologue: write bias terms into the output bias slots (fused kernel then
// atomicAdds the folded-weight sums on top). Must run BEFORE fused kernel.
// ---------------------------------------------------------------------------
__global__ void bias_init_kernel(const float* __restrict__ bu,
                                 const float* __restrict__ bl,
                                 float* __restrict__ out) {
    int i = threadIdx.x;                  // 0..63  (BATCH*N_OUT)
    if (i < BATCH * N_OUT) {
        out[OFF_BU + i] = bu[i];
        out[OFF_BL + i] = bl[i];
    }
}

// ---------------------------------------------------------------------------
// Fat kernel: blocks [0,NR) fold weights into biases (inline 2x2 maxpool),
// blocks [NR,NBLK) stream zeros into the two w_zero regions.
// Both roles coexist on every SM -> read and write HBM streams overlap with
// full-occupancy MLP.
// ---------------------------------------------------------------------------
__global__ __launch_bounds__(R_THREADS)
void fused_kernel(const float* __restrict__ u,
                  const float* __restrict__ l,
                  const float4* __restrict__ wu,
                  const float4* __restrict__ wl,
                  float* __restrict__ out) {
    const int bid = blockIdx.x;
    const int tid = threadIdx.x;

    if (bid >= NR) {
        // ---------------- zero role: contiguous streaming float4 stores ----
        float4* out4 = (float4*)out;
        const float4 zv = make_float4(0.f, 0.f, 0.f, 0.f);
        const long long z0 = (long long)(bid - NR) * Z_CHUNK;
        const long long z1 = min(z0 + Z_CHUNK, TOTAL4);
        for (long long zi = z0 + tid; zi < z1; zi += R_THREADS) {
            long long off = zi & (REGION4 - 1);
            long long oi  = (zi >= REGION4) ? (REGION1_OFF + off) : off;
            __stcs(out4 + oi, zv);
        }
        return;
    }

    // -------------------- reduce role --------------------------------------
    const int b     = bid >= 148 ? 1 : 0;
    const int chunk = bid - b * 148;
    const int o4    = tid & 7;          // which float4 of the 32-wide row
    const int pof   = tid >> 3;         // 0..31

    const int p_begin = chunk * P_PER_BLK;
    const int p_end   = min(p_begin + P_PER_BLK, N_POOL);

    const long long wbase = (long long)b * N_POOL;
    const float* ub = u + (long long)b * N_IN;
    const float* lb = l + (long long)b * N_IN;

    float4 au = make_float4(0.f, 0.f, 0.f, 0.f);
    float4 al = make_float4(0.f, 0.f, 0.f, 0.f);

    for (int p = p_begin + pof; p < p_end; p += 32) {
        // inline 2x2 stride-2 NHWC maxpool
        int c  = p & 127;
        int pw = (p >> 7) & 31;
        int ph = p >> 12;
        int base = (ph << 14) + (pw << 8) + c;   // 2*ph*64*128 + 2*pw*128 + c
        float bu = fmaxf(fmaxf(__ldg(ub + base),        __ldg(ub + base + 128)),
                         fmaxf(__ldg(ub + base + 8192), __ldg(ub + base + 8320)));
        float bl = fmaxf(fmaxf(__ldg(lb + base),        __ldg(lb + base + 128)),
                         fmaxf(__ldg(lb + base + 8192), __ldg(lb + base + 8320)));

        long long row = (wbase + p) * 8 + o4;
        float4 wuv = __ldcs(wu + row);
        float4 wlv = __ldcs(wl + row);

        au.x = fmaf(fmaxf(wuv.x, 0.f), bu, fmaf(fminf(wuv.x, 0.f), bl, au.x));
        au.y = fmaf(fmaxf(wuv.y, 0.f), bu, fmaf(fminf(wuv.y, 0.f), bl, au.y));
        au.z = fmaf(fmaxf(wuv.z, 0.f), bu, fmaf(fminf(wuv.z, 0.f), bl, au.z));
        au.w = fmaf(fmaxf(wuv.w, 0.f), bu, fmaf(fminf(wuv.w, 0.f), bl, au.w));

        al.x = fmaf(fmaxf(wlv.x, 0.f), bl, fmaf(fminf(wlv.x, 0.f), bu, al.x));
        al.y = fmaf(fmaxf(wlv.y, 0.f), bl, fmaf(fminf(wlv.y, 0.f), bu, al.y));
        al.z = fmaf(fmaxf(wlv.z, 0.f), bl, fmaf(fminf(wlv.z, 0.f), bu, al.z));
        al.w = fmaf(fmaxf(wlv.w, 0.f), bl, fmaf(fminf(wlv.w, 0.f), bu, al.w));
    }

    // block-level bias reduction, then global atomics onto pre-initialized slots
    __shared__ float s_u[N_OUT];
    __shared__ float s_l[N_OUT];
    if (tid < N_OUT) { s_u[tid] = 0.0f; s_l[tid] = 0.0f; }
    __syncthreads();

    int ob = o4 * 4;
    atomicAdd(&s_u[ob + 0], au.x);
    atomicAdd(&s_u[ob + 1], au.y);
    atomicAdd(&s_u[ob + 2], au.z);
    atomicAdd(&s_u[ob + 3], au.w);
    atomicAdd(&s_l[ob + 0], al.x);
    atomicAdd(&s_l[ob + 1], al.y);
    atomicAdd(&s_l[ob + 2], al.z);
    atomicAdd(&s_l[ob + 3], al.w);
    __syncthreads();

    if (tid < N_OUT) {
        atomicAdd(&out[OFF_BU + b * N_OUT + tid], s_u[tid]);
        atomicAdd(&out[OFF_BL + b * N_OUT + tid], s_l[tid]);
    }
}

// ---------------------------------------------------------------------------
extern "C" void kernel_launch(void* const* d_in, const int* in_sizes, int n_in,
                              void* d_out, int out_size) {
    // Input order: y, x_0, u_c, l_c, w_out_u, b_out_u, w_out_l, b_out_l
    const float* u_c     = (const float*)d_in[2];
    const float* l_c     = (const float*)d_in[3];
    const float* w_out_u = (const float*)d_in[4];
    const float* b_out_u = (const float*)d_in[5];
    const float* w_out_l = (const float*)d_in[6];
    const float* b_out_l = (const float*)d_in[7];
    float* out = (float*)d_out;

    // 1) Bias slots = b_out_u / b_out_l (fused kernel atomicAdds on top).
    bias_init_kernel<<<1, 64>>>(b_out_u, b_out_l, out);

    // 2) Everything else in one fat kernel: zeroing + maxpool + weight fold.
    fused_kernel<<<NBLK, R_THREADS>>>(u_c, l_c,
                                      (const float4*)w_out_u,
                                      (const float4*)w_out_l, out);
}

// round 6
// speedup vs baseline: 1.0453x; 1.0453x over previous
#include <cuda_runtime.h>

// Fixed shapes from reference setup_inputs
#define BATCH   2
#define H_IN    64
#define W_IN    64
#define C_IN    128
#define N_IN    (H_IN * W_IN * C_IN)          // 524288
#define N_POOL  131072                        // 32*32*128
#define N_OUT   32

// Output layout: [w_zero (B*N_IN*N_OUT)] [b_u_ (B*N_OUT)] [w_zero] [b_l_ (B*N_OUT)]
#define WZ_ELEMS  ((long long)BATCH * N_IN * N_OUT)     // 33554432
#define OFF_BU    (WZ_ELEMS)                            // 33554432
#define OFF_WZ2   (OFF_BU + (long long)BATCH * N_OUT)   // 33554496
#define OFF_BL    (OFF_WZ2 + WZ_ELEMS)                  // 67108928

// float4-granular zero regions (both 16B aligned):
//   region0: float4 [0, 8388608)
//   region1: float4 [8388624, 16777232)   (gap of exactly 16 float4 = bias b_u_)
#define REGION4   8388608LL
#define TOTAL4    (2LL * REGION4)          // 16777216

// One full wave: 296 blocks = 2 CTAs/SM on 148 SMs.
#define NBLK       296
#define R_THREADS  256
#define P_PER_BLK  886                      // ceil(131072/148)
#define Z_CHUNK    56681LL                  // ceil(TOTAL4 / NBLK)

// ---------------------------------------------------------------------------
// Prologue: bias slots = b_out_u / b_out_l (fused kernel atomicAdds on top).
// ---------------------------------------------------------------------------
__global__ void bias_init_kernel(const float* __restrict__ bu,
                                 const float* __restrict__ bl,
                                 float* __restrict__ out) {
    int i = threadIdx.x;                  // 0..63  (BATCH*N_OUT)
    if (i < BATCH * N_OUT) {
        out[OFF_BU + i] = bu[i];
        out[OFF_BL + i] = bl[i];
    }
}

// ---------------------------------------------------------------------------
// Fused two-phase kernel. Phase 1 (all blocks, chip-wide pure READ):
// inline 2x2 maxpool + weight fold + bias atomics. Phase 2 (chip-wide pure
// WRITE): contiguous streaming zero stores. Phases are separated per block so
// the HBM bus runs read-only then write-only, avoiding the ~3.5 TB/s mixed
// r/w wall measured in R2/R3.
// ---------------------------------------------------------------------------
__global__ __launch_bounds__(R_THREADS)
void fused_kernel(const float* __restrict__ u,
                  const float* __restrict__ l,
                  const float4* __restrict__ wu,
                  const float4* __restrict__ wl,
                  float* __restrict__ out) {
    const int bid = blockIdx.x;
    const int tid = threadIdx.x;

    // ---------------- Phase 1: reduce (reads only) --------------------------
    const int b     = (bid >= 148) ? 1 : 0;
    const int chunk = bid - b * 148;
    const int o4    = tid & 7;          // which float4 of the 32-wide N_OUT row
    const int pof   = tid >> 3;         // 0..31

    const int p_begin = chunk * P_PER_BLK;
    const int p_end   = min(p_begin + P_PER_BLK, N_POOL);

    const long long wbase = (long long)b * N_POOL;
    const float* ub = u + (long long)b * N_IN;
    const float* lb = l + (long long)b * N_IN;

    float4 au = make_float4(0.f, 0.f, 0.f, 0.f);
    float4 al = make_float4(0.f, 0.f, 0.f, 0.f);

    for (int p = p_begin + pof; p < p_end; p += 32) {
        // inline 2x2 stride-2 NHWC maxpool
        int c  = p & 127;
        int pw = (p >> 7) & 31;
        int ph = p >> 12;
        int base = (ph << 14) + (pw << 8) + c;   // 2*ph*64*128 + 2*pw*128 + c
        float bu = fmaxf(fmaxf(__ldg(ub + base),        __ldg(ub + base + 128)),
                         fmaxf(__ldg(ub + base + 8192), __ldg(ub + base + 8320)));
        float bl = fmaxf(fmaxf(__ldg(lb + base),        __ldg(lb + base + 128)),
                         fmaxf(__ldg(lb + base + 8192), __ldg(lb + base + 8320)));

        long long row = (wbase + p) * 8 + o4;
        float4 wuv = __ldcs(wu + row);
        float4 wlv = __ldcs(wl + row);

        au.x = fmaf(fmaxf(wuv.x, 0.f), bu, fmaf(fminf(wuv.x, 0.f), bl, au.x));
        au.y = fmaf(fmaxf(wuv.y, 0.f), bu, fmaf(fminf(wuv.y, 0.f), bl, au.y));
        au.z = fmaf(fmaxf(wuv.z, 0.f), bu, fmaf(fminf(wuv.z, 0.f), bl, au.z));
        au.w = fmaf(fmaxf(wuv.w, 0.f), bu, fmaf(fminf(wuv.w, 0.f), bl, au.w));

        al.x = fmaf(fmaxf(wlv.x, 0.f), bl, fmaf(fminf(wlv.x, 0.f), bu, al.x));
        al.y = fmaf(fmaxf(wlv.y, 0.f), bl, fmaf(fminf(wlv.y, 0.f), bu, al.y));
        al.z = fmaf(fmaxf(wlv.z, 0.f), bl, fmaf(fminf(wlv.z, 0.f), bu, al.z));
        al.w = fmaf(fmaxf(wlv.w, 0.f), bl, fmaf(fminf(wlv.w, 0.f), bu, al.w));
    }

    __shared__ float s_u[N_OUT];
    __shared__ float s_l[N_OUT];
    if (tid < N_OUT) { s_u[tid] = 0.0f; s_l[tid] = 0.0f; }
    __syncthreads();

    int ob = o4 * 4;
    atomicAdd(&s_u[ob + 0], au.x);
    atomicAdd(&s_u[ob + 1], au.y);
    atomicAdd(&s_u[ob + 2], au.z);
    atomicAdd(&s_u[ob + 3], au.w);
    atomicAdd(&s_l[ob + 0], al.x);
    atomicAdd(&s_l[ob + 1], al.y);
    atomicAdd(&s_l[ob + 2], al.z);
    atomicAdd(&s_l[ob + 3], al.w);
    __syncthreads();

    if (tid < N_OUT) {
        atomicAdd(&out[OFF_BU + b * N_OUT + tid], s_u[tid]);
        atomicAdd(&out[OFF_BL + b * N_OUT + tid], s_l[tid]);
    }

    // ---------------- Phase 2: zero my contiguous chunk (writes only) -------
    float4* out4 = (float4*)out;
    const float4 zv = make_float4(0.f, 0.f, 0.f, 0.f);
    const long long z0 = (long long)bid * Z_CHUNK;
    const long long z1 = min(z0 + Z_CHUNK, TOTAL4);

    // Address map: region1 starts 16 float4s after region0 ends (bias gap).
    #pragma unroll 4
    for (long long zi = z0 + tid; zi < z1; zi += R_THREADS) {
        long long oi = (zi >= REGION4) ? (zi + 16) : zi;
        __stcs(out4 + oi, zv);
    }
}

// ---------------------------------------------------------------------------
extern "C" void kernel_launch(void* const* d_in, const int* in_sizes, int n_in,
                              void* d_out, int out_size) {
    // Input order: y, x_0, u_c, l_c, w_out_u, b_out_u, w_out_l, b_out_l
    const float* u_c     = (const float*)d_in[2];
    const float* l_c     = (const float*)d_in[3];
    const float* w_out_u = (const float*)d_in[4];
    const float* b_out_u = (const float*)d_in[5];
    const float* w_out_l = (const float*)d_in[6];
    const float* b_out_l = (const float*)d_in[7];
    float* out = (float*)d_out;

    // 1) Bias slots = b_out_u / b_out_l.
    bias_init_kernel<<<1, 64>>>(b_out_u, b_out_l, out);

    // 2) Two-phase fat kernel: read-only fold, then write-only zeroing.
    fused_kernel<<<NBLK, R_THREADS>>>(u_c, l_c,
                                      (const float4*)w_out_u,
                                      (const float4*)w_out_l, out);
}

// round 7
// speedup vs baseline: 1.1526x; 1.1026x over previous
#include <cuda_runtime.h>
#include <cstdint>

// Fixed shapes from reference setup_inputs
#define BATCH   2
#define N_IN    524288                       // 64*64*128
#define N_POOL  131072                       // 32*32*128
#define N_OUT   32

// Output layout (floats): [w_zero 33554432] [b_u_ 64] [w_zero 33554432] [b_l_ 64]
#define WZ_ELEMS  33554432LL
#define OFF_BU    33554432LL
#define OFF_WZ2   33554496LL
#define OFF_BL    67108928LL

// Two 128-MiB zero regions (bytes). Region1 starts right after the b_u_ gap.
#define REGION_BYTES  134217728LL
#define R1_BYTE_OFF   (OFF_WZ2 * 4LL)        // 134217984, 256B-aligned

// One full wave: 296 blocks = 2 CTAs/SM on 148 SMs.
// Blocks [0,148)  -> batch 0 reduce + region0 zeroing
// Blocks [148,296)-> batch 1 reduce + region1 zeroing
#define NBLK        296
#define R_THREADS   256
#define P_PER_BLK   886                      // ceil(131072/148)
#define ZB_PER_BLK  906880LL                 // per-block zero bytes (multiple of 16)
#define BUF_BYTES   32768                    // SMEM zero source for TMA bulk stores

// ---------------------------------------------------------------------------
// Prologue: bias slots = b_out_u / b_out_l (fused kernel atomicAdds on top).
// ---------------------------------------------------------------------------
__global__ void bias_init_kernel(const float* __restrict__ bu,
                                 const float* __restrict__ bl,
                                 float* __restrict__ out) {
    int i = threadIdx.x;                  // 0..63  (BATCH*N_OUT)
    if (i < BATCH * N_OUT) {
        out[OFF_BU + i] = bu[i];
        out[OFF_BL + i] = bl[i];
    }
}

// ---------------------------------------------------------------------------
// Fused kernel:
//   1) zero a 32KiB SMEM buffer, fence to async proxy
//   2) ONE thread fire-and-forgets ~28 cp.async.bulk (SMEM->GMEM) zero stores
//      covering this block's contiguous slice of the w_zero output
//   3) all threads run the read-only maxpool + weight-fold reduction while the
//      TMA engines drain the write stream in the background
//   4) bias atomics; wait_group 0; done
// ---------------------------------------------------------------------------
__global__ __launch_bounds__(R_THREADS)
void fused_kernel(const float* __restrict__ u,
                  const float* __restrict__ l,
                  const float4* __restrict__ wu,
                  const float4* __restrict__ wl,
                  float* __restrict__ out) {
    const int bid = blockIdx.x;
    const int tid = threadIdx.x;

    __shared__ float4 zbuf[BUF_BYTES / 16];     // 32 KiB of zeros
    __shared__ float  s_u[N_OUT];
    __shared__ float  s_l[N_OUT];

    // ---- 1) zero the SMEM source buffer ------------------------------------
    const float4 zv = make_float4(0.f, 0.f, 0.f, 0.f);
    #pragma unroll
    for (int i = tid; i < BUF_BYTES / 16; i += R_THREADS) zbuf[i] = zv;
    if (tid < N_OUT) { s_u[tid] = 0.0f; s_l[tid] = 0.0f; }
    __syncthreads();

    const int b     = (bid >= 148) ? 1 : 0;
    const int chunk = bid - b * 148;

    // ---- 2) issue TMA bulk zero stores (single thread, fire-and-forget) ----
    if (tid == 0) {
        asm volatile("fence.proxy.async.shared::cta;" ::: "memory");
        uint32_t saddr;
        asm("{ .reg .u64 t; cvta.to.shared.u64 t, %1; cvt.u32.u64 %0, t; }"
            : "=r"(saddr) : "l"(zbuf));
        char* gbase = (char*)out + (b ? R1_BYTE_OFF : 0LL);
        long long g0 = (long long)chunk * ZB_PER_BLK;
        long long g1 = g0 + ZB_PER_BLK;
        if (g1 > REGION_BYTES) g1 = REGION_BYTES;
        for (long long g = g0; g < g1; g += BUF_BYTES) {
            uint32_t sz = (uint32_t)((g1 - g) < BUF_BYTES ? (g1 - g) : BUF_BYTES);
            asm volatile(
                "cp.async.bulk.global.shared::cta.bulk_group [%0], [%1], %2;"
                :: "l"(gbase + g), "r"(saddr), "r"(sz) : "memory");
        }
        asm volatile("cp.async.bulk.commit_group;" ::: "memory");
    }

    // ---- 3) read-only reduce (overlaps with TMA write drain) ---------------
    const int o4  = tid & 7;          // which float4 of the 32-wide N_OUT row
    const int pof = tid >> 3;         // 0..31

    const int p_begin = chunk * P_PER_BLK;
    const int p_end   = min(p_begin + P_PER_BLK, N_POOL);

    const long long wbase = (long long)b * N_POOL;
    const float* ub = u + (long long)b * N_IN;
    const float* lb = l + (long long)b * N_IN;

    float4 au = make_float4(0.f, 0.f, 0.f, 0.f);
    float4 al = make_float4(0.f, 0.f, 0.f, 0.f);

    for (int p = p_begin + pof; p < p_end; p += 32) {
        // inline 2x2 stride-2 NHWC maxpool
        int c  = p & 127;
        int pw = (p >> 7) & 31;
        int ph = p >> 12;
        int base = (ph << 14) + (pw << 8) + c;   // 2*ph*64*128 + 2*pw*128 + c
        float bu = fmaxf(fmaxf(__ldg(ub + base),        __ldg(ub + base + 128)),
                         fmaxf(__ldg(ub + base + 8192), __ldg(ub + base + 8320)));
        float bl = fmaxf(fmaxf(__ldg(lb + base),        __ldg(lb + base + 128)),
                         fmaxf(__ldg(lb + base + 8192), __ldg(lb + base + 8320)));

        long long row = (wbase + p) * 8 + o4;
        float4 wuv = __ldcs(wu + row);
        float4 wlv = __ldcs(wl + row);

        au.x = fmaf(fmaxf(wuv.x, 0.f), bu, fmaf(fminf(wuv.x, 0.f), bl, au.x));
        au.y = fmaf(fmaxf(wuv.y, 0.f), bu, fmaf(fminf(wuv.y, 0.f), bl, au.y));
        au.z = fmaf(fmaxf(wuv.z, 0.f), bu, fmaf(fminf(wuv.z, 0.f), bl, au.z));
        au.w = fmaf(fmaxf(wuv.w, 0.f), bu, fmaf(fminf(wuv.w, 0.f), bl, au.w));

        al.x = fmaf(fmaxf(wlv.x, 0.f), bl, fmaf(fminf(wlv.x, 0.f), bu, al.x));
        al.y = fmaf(fmaxf(wlv.y, 0.f), bl, fmaf(fminf(wlv.y, 0.f), bu, al.y));
        al.z = fmaf(fmaxf(wlv.z, 0.f), bl, fmaf(fminf(wlv.z, 0.f), bu, al.z));
        al.w = fmaf(fmaxf(wlv.w, 0.f), bl, fmaf(fminf(wlv.w, 0.f), bu, al.w));
    }

    // ---- 4) block-level bias reduction + global atomics ---------------------
    int ob = o4 * 4;
    atomicAdd(&s_u[ob + 0], au.x);
    atomicAdd(&s_u[ob + 1], au.y);
    atomicAdd(&s_u[ob + 2], au.z);
    atomicAdd(&s_u[ob + 3], au.w);
    atomicAdd(&s_l[ob + 0], al.x);
    atomicAdd(&s_l[ob + 1], al.y);
    atomicAdd(&s_l[ob + 2], al.z);
    atomicAdd(&s_l[ob + 3], al.w);
    __syncthreads();

    if (tid < N_OUT) {
        atomicAdd(&out[OFF_BU + b * N_OUT + tid], s_u[tid]);
        atomicAdd(&out[OFF_BL + b * N_OUT + tid], s_l[tid]);
    }

    // ---- 5) drain TMA stores before SMEM goes away --------------------------
    if (tid == 0) {
        asm volatile("cp.async.bulk.wait_group 0;" ::: "memory");
    }
    __syncthreads();
}

// ---------------------------------------------------------------------------
extern "C" void kernel_launch(void* const* d_in, const int* in_sizes, int n_in,
                              void* d_out, int out_size) {
    // Input order: y, x_0, u_c, l_c, w_out_u, b_out_u, w_out_l, b_out_l
    const float* u_c     = (const float*)d_in[2];
    const float* l_c     = (const float*)d_in[3];
    const float* w_out_u = (const float*)d_in[4];
    const float* b_out_u = (const float*)d_in[5];
    const float* w_out_l = (const float*)d_in[6];
    const float* b_out_l = (const float*)d_in[7];
    float* out = (float*)d_out;

    // 1) Bias slots = b_out_u / b_out_l.
    bias_init_kernel<<<1, 64>>>(b_out_u, b_out_l, out);

    // 2) Fused: TMA bulk zeroing (background) + maxpool/weight-fold reduce.
    fused_kernel<<<NBLK, R_THREADS>>>(u_c, l_c,
                                      (const float4*)w_out_u,
                                      (const float4*)w_out_l, out);
}

// round 8
// speedup vs baseline: 1.2548x; 1.0887x over previous
#include <cuda_runtime.h>
#include <cstdint>

// Fixed shapes from reference setup_inputs
#define BATCH   2
#define N_IN    524288                       // 64*64*128
#define N_POOL  131072                       // 32*32*128
#define N_OUT   32

// Output layout (floats): [w_zero 33554432] [b_u_ 64] [w_zero 33554432] [b_l_ 64]
#define OFF_BU    33554432LL
#define OFF_WZ2   33554496LL
#define OFF_BL    67108928LL

// Two 128-MiB zero regions (bytes). Region1 starts right after the b_u_ gap.
#define REGION_BYTES  134217728LL
#define R1_BYTE_OFF   (OFF_WZ2 * 4LL)        // 134217984, 16B-aligned

// 592 blocks = 4 CTAs/SM on 148 SMs (one wave).
// Blocks [0,296)   -> batch 0 ; blocks [296,592) -> batch 1
#define NBLK        592
#define BLK_PER_B   296
#define R_THREADS   256
#define P_PER_BLK   443                      // ceil(131072/296)
#define ZB_PER_BLK  453440LL                 // ceil(REGION/296) rounded to 16B
#define BUF_BYTES   32768                    // SMEM zero source for TMA bulk stores

// Cross-block reduction scratch (zero-initialized; reset by last block each run)
__device__ float        g_pu[BATCH][N_OUT];
__device__ float        g_pl[BATCH][N_OUT];
__device__ unsigned int g_cnt[BATCH];

// ---------------------------------------------------------------------------
// Single fused kernel:
//   1) zero 32KiB SMEM buffer; fence to async proxy
//   2) one thread fire-and-forgets ~14 cp.async.bulk zero stores (32KiB each)
//      covering this block's contiguous slice of the w_zero output
//   3) all threads run the read-only maxpool + weight-fold reduction while the
//      TMA engines drain the write stream in the background
//   4) block partials -> global scratch atomics; LAST block per batch adds the
//      bias and writes the 64 output floats, then resets scratch (replay-safe)
//   5) cp.async.bulk.wait_group 0
// ---------------------------------------------------------------------------
__global__ __launch_bounds__(R_THREADS)
void fused_kernel(const float* __restrict__ u,
                  const float* __restrict__ l,
                  const float4* __restrict__ wu,
                  const float4* __restrict__ wl,
                  const float* __restrict__ bias_u,
                  const float* __restrict__ bias_l,
                  float* __restrict__ out) {
    const int bid = blockIdx.x;
    const int tid = threadIdx.x;

    __shared__ float4 zbuf[BUF_BYTES / 16];     // 32 KiB of zeros
    __shared__ float  s_u[N_OUT];
    __shared__ float  s_l[N_OUT];
    __shared__ int    s_last;

    // ---- 1) zero the SMEM source buffer ------------------------------------
    const float4 zv = make_float4(0.f, 0.f, 0.f, 0.f);
    #pragma unroll
    for (int i = tid; i < BUF_BYTES / 16; i += R_THREADS) zbuf[i] = zv;
    if (tid < N_OUT) { s_u[tid] = 0.0f; s_l[tid] = 0.0f; }
    __syncthreads();

    const int b     = (bid >= BLK_PER_B) ? 1 : 0;
    const int chunk = bid - b * BLK_PER_B;

    // ---- 2) issue TMA bulk zero stores (single thread, fire-and-forget) ----
    if (tid == 0) {
        asm volatile("fence.proxy.async.shared::cta;" ::: "memory");
        uint32_t saddr;
        asm("{ .reg .u64 t; cvta.to.shared.u64 t, %1; cvt.u32.u64 %0, t; }"
            : "=r"(saddr) : "l"(zbuf));
        char* gbase = (char*)out + (b ? R1_BYTE_OFF : 0LL);
        long long g0 = (long long)chunk * ZB_PER_BLK;
        long long g1 = g0 + ZB_PER_BLK;
        if (g1 > REGION_BYTES) g1 = REGION_BYTES;
        for (long long g = g0; g < g1; g += BUF_BYTES) {
            uint32_t sz = (uint32_t)((g1 - g) < BUF_BYTES ? (g1 - g) : BUF_BYTES);
            asm volatile(
                "cp.async.bulk.global.shared::cta.bulk_group [%0], [%1], %2;"
                :: "l"(gbase + g), "r"(saddr), "r"(sz) : "memory");
        }
        asm volatile("cp.async.bulk.commit_group;" ::: "memory");
    }

    // ---- 3) read-only reduce (overlaps with TMA write drain) ---------------
    const int o4  = tid & 7;          // which float4 of the 32-wide N_OUT row
    const int pof = tid >> 3;         // 0..31

    const int p_begin = chunk * P_PER_BLK;
    const int p_end   = min(p_begin + P_PER_BLK, N_POOL);

    const long long wbase = (long long)b * N_POOL;
    const float* ub = u + (long long)b * N_IN;
    const float* lb = l + (long long)b * N_IN;

    float4 au = make_float4(0.f, 0.f, 0.f, 0.f);
    float4 al = make_float4(0.f, 0.f, 0.f, 0.f);

    for (int p = p_begin + pof; p < p_end; p += 32) {
        // inline 2x2 stride-2 NHWC maxpool
        int c  = p & 127;
        int pw = (p >> 7) & 31;
        int ph = p >> 12;
        int base = (ph << 14) + (pw << 8) + c;   // 2*ph*64*128 + 2*pw*128 + c
        float bu = fmaxf(fmaxf(__ldg(ub + base),        __ldg(ub + base + 128)),
                         fmaxf(__ldg(ub + base + 8192), __ldg(ub + base + 8320)));
        float bl = fmaxf(fmaxf(__ldg(lb + base),        __ldg(lb + base + 128)),
                         fmaxf(__ldg(lb + base + 8192), __ldg(lb + base + 8320)));

        long long row = (wbase + p) * 8 + o4;
        float4 wuv = __ldcs(wu + row);
        float4 wlv = __ldcs(wl + row);

        au.x = fmaf(fmaxf(wuv.x, 0.f), bu, fmaf(fminf(wuv.x, 0.f), bl, au.x));
        au.y = fmaf(fmaxf(wuv.y, 0.f), bu, fmaf(fminf(wuv.y, 0.f), bl, au.y));
        au.z = fmaf(fmaxf(wuv.z, 0.f), bu, fmaf(fminf(wuv.z, 0.f), bl, au.z));
        au.w = fmaf(fmaxf(wuv.w, 0.f), bu, fmaf(fminf(wuv.w, 0.f), bl, au.w));

        al.x = fmaf(fmaxf(wlv.x, 0.f), bl, fmaf(fminf(wlv.x, 0.f), bu, al.x));
        al.y = fmaf(fmaxf(wlv.y, 0.f), bl, fmaf(fminf(wlv.y, 0.f), bu, al.y));
        al.z = fmaf(fmaxf(wlv.z, 0.f), bl, fmaf(fminf(wlv.z, 0.f), bu, al.z));
        al.w = fmaf(fmaxf(wlv.w, 0.f), bl, fmaf(fminf(wlv.w, 0.f), bu, al.w));
    }

    // ---- 4) block partials -> global scratch; last block writes output -----
    int ob = o4 * 4;
    atomicAdd(&s_u[ob + 0], au.x);
    atomicAdd(&s_u[ob + 1], au.y);
    atomicAdd(&s_u[ob + 2], au.z);
    atomicAdd(&s_u[ob + 3], au.w);
    atomicAdd(&s_l[ob + 0], al.x);
    atomicAdd(&s_l[ob + 1], al.y);
    atomicAdd(&s_l[ob + 2], al.z);
    atomicAdd(&s_l[ob + 3], al.w);
    __syncthreads();

    if (tid < N_OUT) {
        atomicAdd(&g_pu[b][tid], s_u[tid]);
        atomicAdd(&g_pl[b][tid], s_l[tid]);
    }
    __threadfence();
    if (tid == 0) {
        unsigned t = atomicAdd(&g_cnt[b], 1u);
        s_last = (t == BLK_PER_B - 1u) ? 1 : 0;
    }
    __syncthreads();

    if (s_last) {
        if (tid < N_OUT) {
            float su = g_pu[b][tid];
            float sl = g_pl[b][tid];
            out[OFF_BU + b * N_OUT + tid] = su + __ldg(bias_u + b * N_OUT + tid);
            out[OFF_BL + b * N_OUT + tid] = sl + __ldg(bias_l + b * N_OUT + tid);
            // reset scratch for the next graph replay
            g_pu[b][tid] = 0.0f;
            g_pl[b][tid] = 0.0f;
        }
        __syncthreads();
        if (tid == 0) {
            __threadfence();
            g_cnt[b] = 0u;
        }
    }

    // ---- 5) drain TMA stores before SMEM goes away --------------------------
    if (tid == 0) {
        asm volatile("cp.async.bulk.wait_group 0;" ::: "memory");
    }
    __syncthreads();
}

// ---------------------------------------------------------------------------
extern "C" void kernel_launch(void* const* d_in, const int* in_sizes, int n_in,
                              void* d_out, int out_size) {
    // Input order: y, x_0, u_c, l_c, w_out_u, b_out_u, w_out_l, b_out_l
    const float* u_c     = (const float*)d_in[2];
    const float* l_c     = (const float*)d_in[3];
    const float* w_out_u = (const float*)d_in[4];
    const float* b_out_u = (const float*)d_in[5];
    const float* w_out_l = (const float*)d_in[6];
    const float* b_out_l = (const float*)d_in[7];
    float* out = (float*)d_out;

    fused_kernel<<<NBLK, R_THREADS>>>(u_c, l_c,
                                      (const float4*)w_out_u,
                                      (const float4*)w_out_l,
                                      b_out_u, b_out_l, out);
}